// round 1
// baseline (speedup 1.0000x reference)
#include <cuda_runtime.h>
#include <cuda_bf16.h>
#include <math.h>

// ---------------- problem constants ----------------
#define NTOK 16384      // B*T = 4*4096
#define HDIM 1024
#define NEXP 8
#define TOPK 2
#define FDIM 1024

#define TM 64
#define TN 64
#define KB 16

#define NASSIGN (NTOK * TOPK)                 // 32768 (exact)
#define PADDED_CAP (NASSIGN + NEXP * TM)      // 33280 (per-expert 64-align pad)

// ---------------- device scratch (static; no allocs) ----------------
__device__ float g_hid[(size_t)PADDED_CAP * FDIM];      // SwiGLU hidden, per assignment row
__device__ float g_contrib[(size_t)PADDED_CAP * HDIM];  // scaled expert output, per row
__device__ int   g_perm[PADDED_CAP];                    // row -> token (-1 = pad)
__device__ float g_gw[PADDED_CAP];                      // row -> gate weight
__device__ int   g_rowof[NTOK * TOPK];                  // (token,k) -> row
__device__ int   g_tok_e[NTOK * TOPK];
__device__ float g_tok_w[NTOK * TOPK];
__device__ int   g_count[NEXP];
__device__ int   g_cursor[NEXP];
__device__ float g_usage[NEXP];
__device__ int   g_offset[NEXP + 1];

// ---------------- K0: init ----------------
__global__ void init_kernel() {
    int idx = blockIdx.x * blockDim.x + threadIdx.x;
    if (idx < PADDED_CAP) g_perm[idx] = -1;
    if (idx < NEXP) { g_count[idx] = 0; g_cursor[idx] = 0; g_usage[idx] = 0.f; }
}

// ---------------- K1: router (4 tokens/block, warp per token) ----------------
__global__ __launch_bounds__(128) void router_kernel(const float* __restrict__ x,
                                                     const float* __restrict__ rw) {
    __shared__ float srw[NEXP * HDIM];   // 32KB
    __shared__ float sprob[NEXP];
    int tid = threadIdx.x;
    for (int i = tid; i < NEXP * HDIM; i += 128) srw[i] = rw[i];
    if (tid < NEXP) sprob[tid] = 0.f;
    __syncthreads();

    int warp = tid >> 5, lane = tid & 31;
    int t = blockIdx.x * 4 + warp;

    float acc[NEXP];
#pragma unroll
    for (int e = 0; e < NEXP; e++) acc[e] = 0.f;

    const float* xp = x + (size_t)t * HDIM;
    for (int j = lane; j < HDIM; j += 32) {
        float xv = xp[j];
#pragma unroll
        for (int e = 0; e < NEXP; e++) acc[e] += xv * srw[e * HDIM + j];
    }
#pragma unroll
    for (int e = 0; e < NEXP; e++) {
#pragma unroll
        for (int off = 16; off; off >>= 1)
            acc[e] += __shfl_xor_sync(0xFFFFFFFFu, acc[e], off);
    }

    if (lane == 0) {
        float mx = acc[0];
#pragma unroll
        for (int e = 1; e < NEXP; e++) mx = fmaxf(mx, acc[e]);
        float p[NEXP]; float s = 0.f;
#pragma unroll
        for (int e = 0; e < NEXP; e++) { p[e] = expf(acc[e] - mx); s += p[e]; }
        float inv = 1.f / s;
#pragma unroll
        for (int e = 0; e < NEXP; e++) p[e] *= inv;

        // top-2 (stable: earliest index wins ties, matching sorted-descending top_k)
        int e1 = 0;
#pragma unroll
        for (int e = 1; e < NEXP; e++) if (p[e] > p[e1]) e1 = e;
        int e2 = (e1 == 0) ? 1 : 0;
#pragma unroll
        for (int e = 0; e < NEXP; e++) if (e != e1 && p[e] > p[e2]) e2 = e;

        float ws = p[e1] + p[e2];
        g_tok_e[2 * t + 0] = e1; g_tok_w[2 * t + 0] = p[e1] / ws;
        g_tok_e[2 * t + 1] = e2; g_tok_w[2 * t + 1] = p[e2] / ws;
        atomicAdd(&g_count[e1], 1);
        atomicAdd(&g_count[e2], 1);
#pragma unroll
        for (int e = 0; e < NEXP; e++) atomicAdd(&sprob[e], p[e]);
    }
    __syncthreads();
    if (tid < NEXP) atomicAdd(&g_usage[tid], sprob[tid]);
}

// ---------------- K2: scan + lb_loss ----------------
__global__ void scan_kernel(float* lb_out, int write_lb) {
    int off = 0;
    for (int e = 0; e < NEXP; e++) {
        g_offset[e] = off;
        off += ((g_count[e] + TM - 1) / TM) * TM;
    }
    g_offset[NEXP] = off;
    if (write_lb) {
        float s = 0.f;
        for (int e = 0; e < NEXP; e++) {
            float u = g_usage[e] / (float)NTOK;
            s += u * u;
        }
        *lb_out = 0.01f * (float)NEXP * s;
    }
}

// ---------------- K3: placement ----------------
__global__ void place_kernel() {
    int t = blockIdx.x * blockDim.x + threadIdx.x;
    if (t >= NTOK) return;
#pragma unroll
    for (int k = 0; k < TOPK; k++) {
        int e = g_tok_e[2 * t + k];
        int pos = atomicAdd(&g_cursor[e], 1);
        int row = g_offset[e] + pos;
        g_perm[row] = t;
        g_gw[row] = g_tok_w[2 * t + k];
        g_rowof[2 * t + k] = row;
    }
}

// ---------------- K4: GEMM A  hid = silu(X@gateT) * (X@upT) ----------------
__global__ __launch_bounds__(256) void gemmA_kernel(const float* __restrict__ x,
                                                    const float* __restrict__ gate_w,
                                                    const float* __restrict__ up_w) {
    int f0 = blockIdx.x * TN;
    int row0 = blockIdx.y * TM;
    if (row0 >= g_offset[NEXP]) return;
    int e = 0;
    while (g_offset[e + 1] <= row0) e++;

    __shared__ float As[KB][TM];
    __shared__ float Bg[KB][TN];
    __shared__ float Bu[KB][TN];
    __shared__ int toks[TM];

    int tid = threadIdx.x;
    if (tid < TM) toks[tid] = g_perm[row0 + tid];
    __syncthreads();

    int r  = tid >> 2;           // 0..63
    int kq = (tid & 3) * 4;      // 0,4,8,12
    int ty = tid >> 4, tx = tid & 15;

    int tokr = toks[r];
    const float* aptr = x + (size_t)(tokr < 0 ? 0 : tokr) * HDIM;
    const float* gptr = gate_w + ((size_t)e * FDIM + f0 + r) * HDIM;
    const float* uptr = up_w   + ((size_t)e * FDIM + f0 + r) * HDIM;
    bool aval = (tokr >= 0);

    float accg[4][4], accu[4][4];
#pragma unroll
    for (int i = 0; i < 4; i++)
#pragma unroll
        for (int j = 0; j < 4; j++) { accg[i][j] = 0.f; accu[i][j] = 0.f; }

    float4 av = aval ? *(const float4*)(aptr + kq) : make_float4(0.f, 0.f, 0.f, 0.f);
    float4 gv = *(const float4*)(gptr + kq);
    float4 uv = *(const float4*)(uptr + kq);

    const int NCHUNK = HDIM / KB;
    for (int kc = 0; kc < NCHUNK; kc++) {
        As[kq + 0][r] = av.x; As[kq + 1][r] = av.y; As[kq + 2][r] = av.z; As[kq + 3][r] = av.w;
        Bg[kq + 0][r] = gv.x; Bg[kq + 1][r] = gv.y; Bg[kq + 2][r] = gv.z; Bg[kq + 3][r] = gv.w;
        Bu[kq + 0][r] = uv.x; Bu[kq + 1][r] = uv.y; Bu[kq + 2][r] = uv.z; Bu[kq + 3][r] = uv.w;
        __syncthreads();

        if (kc + 1 < NCHUNK) {
            int k0n = (kc + 1) * KB + kq;
            av = aval ? *(const float4*)(aptr + k0n) : make_float4(0.f, 0.f, 0.f, 0.f);
            gv = *(const float4*)(gptr + k0n);
            uv = *(const float4*)(uptr + k0n);
        }

#pragma unroll
        for (int k = 0; k < KB; k++) {
            float4 a  = *(const float4*)&As[k][ty * 4];
            float4 bg = *(const float4*)&Bg[k][tx * 4];
            float4 bu = *(const float4*)&Bu[k][tx * 4];
            float ar[4] = {a.x, a.y, a.z, a.w};
            float bgr[4] = {bg.x, bg.y, bg.z, bg.w};
            float bur[4] = {bu.x, bu.y, bu.z, bu.w};
#pragma unroll
            for (int i = 0; i < 4; i++)
#pragma unroll
                for (int j = 0; j < 4; j++) {
                    accg[i][j] += ar[i] * bgr[j];
                    accu[i][j] += ar[i] * bur[j];
                }
        }
        __syncthreads();
    }

#pragma unroll
    for (int i = 0; i < 4; i++) {
        int row = row0 + ty * 4 + i;
#pragma unroll
        for (int j = 0; j < 4; j++) {
            int f = f0 + tx * 4 + j;
            float g = accg[i][j];
            float hidv = (g / (1.f + expf(-g))) * accu[i][j];  // silu(g)*u
            g_hid[(size_t)row * FDIM + f] = hidv;
        }
    }
}

// ---------------- K5: GEMM B  contrib = gw * (hid @ downT) ----------------
__global__ __launch_bounds__(256) void gemmB_kernel(const float* __restrict__ down_w) {
    int h0 = blockIdx.x * TN;
    int row0 = blockIdx.y * TM;
    if (row0 >= g_offset[NEXP]) return;
    int e = 0;
    while (g_offset[e + 1] <= row0) e++;

    __shared__ float As[KB][TM];
    __shared__ float Bs[KB][TN];

    int tid = threadIdx.x;
    int r  = tid >> 2;
    int kq = (tid & 3) * 4;
    int ty = tid >> 4, tx = tid & 15;

    const float* aptr = g_hid + (size_t)(row0 + r) * FDIM;
    const float* bptr = down_w + ((size_t)e * HDIM + h0 + r) * FDIM;

    float acc[4][4];
#pragma unroll
    for (int i = 0; i < 4; i++)
#pragma unroll
        for (int j = 0; j < 4; j++) acc[i][j] = 0.f;

    float4 av = *(const float4*)(aptr + kq);
    float4 bv = *(const float4*)(bptr + kq);

    const int NCHUNK = FDIM / KB;
    for (int kc = 0; kc < NCHUNK; kc++) {
        As[kq + 0][r] = av.x; As[kq + 1][r] = av.y; As[kq + 2][r] = av.z; As[kq + 3][r] = av.w;
        Bs[kq + 0][r] = bv.x; Bs[kq + 1][r] = bv.y; Bs[kq + 2][r] = bv.z; Bs[kq + 3][r] = bv.w;
        __syncthreads();

        if (kc + 1 < NCHUNK) {
            int k0n = (kc + 1) * KB + kq;
            av = *(const float4*)(aptr + k0n);
            bv = *(const float4*)(bptr + k0n);
        }

#pragma unroll
        for (int k = 0; k < KB; k++) {
            float4 a = *(const float4*)&As[k][ty * 4];
            float4 b = *(const float4*)&Bs[k][tx * 4];
            float ar[4] = {a.x, a.y, a.z, a.w};
            float br[4] = {b.x, b.y, b.z, b.w};
#pragma unroll
            for (int i = 0; i < 4; i++)
#pragma unroll
                for (int j = 0; j < 4; j++) acc[i][j] += ar[i] * br[j];
        }
        __syncthreads();
    }

#pragma unroll
    for (int i = 0; i < 4; i++) {
        int row = row0 + ty * 4 + i;
        float w = g_gw[row];
#pragma unroll
        for (int j = 0; j < 4; j++) {
            int h = h0 + tx * 4 + j;
            g_contrib[(size_t)row * HDIM + h] = w * acc[i][j];
        }
    }
}

// ---------------- K6: combine (atomic-free, deterministic) ----------------
__global__ void combine_kernel(float* __restrict__ out) {
    int idx = blockIdx.x * blockDim.x + threadIdx.x;   // over NTOK * HDIM/4
    if (idx >= NTOK * (HDIM / 4)) return;
    int n = idx >> 8;                 // HDIM/4 = 256 float4 per token
    int hq = (idx & 255) * 4;
    int r0 = g_rowof[2 * n + 0];
    int r1 = g_rowof[2 * n + 1];
    float4 c0 = *(const float4*)&g_contrib[(size_t)r0 * HDIM + hq];
    float4 c1 = *(const float4*)&g_contrib[(size_t)r1 * HDIM + hq];
    float4 o;
    o.x = c0.x + c1.x; o.y = c0.y + c1.y; o.z = c0.z + c1.z; o.w = c0.w + c1.w;
    *(float4*)&out[(size_t)n * HDIM + hq] = o;
}

// ---------------- launch ----------------
extern "C" void kernel_launch(void* const* d_in, const int* in_sizes, int n_in,
                              void* d_out, int out_size) {
    const float* x       = (const float*)d_in[0];
    const float* rw      = (const float*)d_in[1];
    const float* gate_w  = (const float*)d_in[2];
    const float* up_w    = (const float*)d_in[3];
    const float* down_w  = (const float*)d_in[4];
    float* out = (float*)d_out;

    int write_lb = (out_size > NTOK * HDIM) ? 1 : 0;
    float* lb_ptr = out + (size_t)NTOK * HDIM;

    init_kernel<<<(PADDED_CAP + 255) / 256, 256>>>();
    router_kernel<<<NTOK / 4, 128>>>(x, rw);
    scan_kernel<<<1, 1>>>(lb_ptr, write_lb);
    place_kernel<<<NTOK / 256, 256>>>();

    dim3 gA(FDIM / TN, PADDED_CAP / TM);   // (16, 520)
    gemmA_kernel<<<gA, 256>>>(x, gate_w, up_w);
    dim3 gB(HDIM / TN, PADDED_CAP / TM);   // (16, 520)
    gemmB_kernel<<<gB, 256>>>(down_w);

    combine_kernel<<<(NTOK * (HDIM / 4) + 255) / 256, 256>>>(out);
}